// round 11
// baseline (speedup 1.0000x reference)
#include <cuda_runtime.h>
#include <math.h>

// ---------------------------------------------------------------------------
// LocalWindowAttentionFusion — fp32, 128x128 double-buffered GEMMs (8x8 uTile)
// attention: 8x8 pixel tile x 2-head group, 106KB smem -> 2 CTA/SM
//   B=2, H=W=200, C1=64, C2=256, C3=256, HEADS=8, HD=32, WS=7, PAD=3
// ---------------------------------------------------------------------------

#define HWC   40000          // H*W
#define PTOT  80000          // B*H*W
#define HDIM  200
#define WDIM  200
#define NPOS  196            // 14*14 halo positions
#define STR   68             // smem row stride for 64ch group (mult of 4)
#define ATTN_SMEM (2 * NPOS * STR * 4)

// -------- scratch (device globals: allocation inside kernel_launch is banned)
__device__ float g_Qb[(size_t)PTOT * 256];
__device__ float g_Kb[(size_t)PTOT * 256];
__device__ float g_Vb[(size_t)PTOT * 256];
__device__ float g_Rb[(size_t)PTOT * 256];
__device__ float g_At[(size_t)PTOT * 256];
__device__ float g_Z1[(size_t)PTOT * 256];
__device__ float g_X [(size_t)PTOT * 256];
__device__ float g_Y [(size_t)PTOT * 1024];
__device__ float g_Z2[(size_t)PTOT * 256];

// ---------------------------------------------------------------------------
// fp32 GEMM producing pixel-major C[p][m], double-buffered smem.
//   X_CHW : X is channel-major X[k][p] (per batch, ldX = Plen), else X[p][k]
//   W_MK  : weight stored W[m][k] (torch conv style), else W[k][m]
// BM=128, BP=128, BK=16, 256 threads, 8x8 micro-tile / thread.
// ---------------------------------------------------------------------------
template<bool X_CHW, bool W_MK, bool HAS_BIAS, bool HAS_RELU, bool HAS_ADD>
__global__ __launch_bounds__(256)
void gemm_k(const float* __restrict__ X, const float* __restrict__ W,
            const float* __restrict__ bias, const float* __restrict__ addin,
            float* __restrict__ C, int M, int Kd, int Plen, size_t xBatchStride)
{
    __shared__ float As[2][16][132];   // [k][p]
    __shared__ float Bs[2][16][132];   // [k][m]

    const int t     = threadIdx.x;
    const int tx    = t & 15;          // m direction
    const int ty    = t >> 4;          // p direction
    const int m_sub = tx * 8;
    const int p_sub = ty * 8;
    const int m0    = blockIdx.x * 128;
    const int p0    = blockIdx.y * 128;
    const int z     = blockIdx.z;
    const float* Xb = X + (size_t)z * xBatchStride;

    auto loadTile = [&](int k0, int buf) {
        if (X_CHW) {
            #pragma unroll
            for (int r = 0; r < 2; r++) {
                int idx = t + r * 256;           // 512 float4 per tile
                int kk  = idx >> 5;
                int pp  = (idx & 31) * 4;
                int p   = p0 + pp;
                const float* src = Xb + (size_t)(k0 + kk) * Plen + p;
                float4 v;
                if (p + 3 < Plen) {
                    v = *(const float4*)src;
                } else {
                    v.x = (p + 0 < Plen) ? src[0] : 0.f;
                    v.y = (p + 1 < Plen) ? src[1] : 0.f;
                    v.z = (p + 2 < Plen) ? src[2] : 0.f;
                    v.w = (p + 3 < Plen) ? src[3] : 0.f;
                }
                *(float4*)&As[buf][kk][pp] = v;
            }
        } else {
            #pragma unroll
            for (int r = 0; r < 2; r++) {
                int idx = t + r * 256;
                int pp  = idx >> 2;              // 0..127
                int kk  = (idx & 3) * 4;
                float4 v = *(const float4*)(Xb + (size_t)(p0 + pp) * Kd + k0 + kk);
                As[buf][kk + 0][pp] = v.x;
                As[buf][kk + 1][pp] = v.y;
                As[buf][kk + 2][pp] = v.z;
                As[buf][kk + 3][pp] = v.w;
            }
        }
        if (W_MK) {
            #pragma unroll
            for (int r = 0; r < 2; r++) {
                int idx = t + r * 256;
                int mm  = idx >> 2;              // 0..127
                int kk  = (idx & 3) * 4;
                float4 v = *(const float4*)(W + (size_t)(m0 + mm) * Kd + k0 + kk);
                Bs[buf][kk + 0][mm] = v.x;
                Bs[buf][kk + 1][mm] = v.y;
                Bs[buf][kk + 2][mm] = v.z;
                Bs[buf][kk + 3][mm] = v.w;
            }
        } else {
            #pragma unroll
            for (int r = 0; r < 2; r++) {
                int idx = t + r * 256;
                int kk  = idx >> 5;
                int mm  = (idx & 31) * 4;
                *(float4*)&Bs[buf][kk][mm] =
                    *(const float4*)(W + (size_t)(k0 + kk) * M + m0 + mm);
            }
        }
    };

    float4 acc[8][2];
    #pragma unroll
    for (int i = 0; i < 8; i++) {
        acc[i][0] = make_float4(0.f, 0.f, 0.f, 0.f);
        acc[i][1] = make_float4(0.f, 0.f, 0.f, 0.f);
    }

    int buf = 0;
    loadTile(0, 0);
    __syncthreads();

    for (int k0 = 16; k0 <= Kd; k0 += 16) {
        if (k0 < Kd) loadTile(k0, buf ^ 1);   // prefetch next tile into other buffer

        #pragma unroll
        for (int kk = 0; kk < 16; kk++) {
            float4 b0 = *(float4*)&Bs[buf][kk][m_sub];
            float4 b1 = *(float4*)&Bs[buf][kk][m_sub + 4];
            float4 a0 = *(float4*)&As[buf][kk][p_sub];
            float4 a1 = *(float4*)&As[buf][kk][p_sub + 4];
            float  a[8] = {a0.x, a0.y, a0.z, a0.w, a1.x, a1.y, a1.z, a1.w};
            #pragma unroll
            for (int i = 0; i < 8; i++) {
                acc[i][0].x = fmaf(a[i], b0.x, acc[i][0].x);
                acc[i][0].y = fmaf(a[i], b0.y, acc[i][0].y);
                acc[i][0].z = fmaf(a[i], b0.z, acc[i][0].z);
                acc[i][0].w = fmaf(a[i], b0.w, acc[i][0].w);
                acc[i][1].x = fmaf(a[i], b1.x, acc[i][1].x);
                acc[i][1].y = fmaf(a[i], b1.y, acc[i][1].y);
                acc[i][1].z = fmaf(a[i], b1.z, acc[i][1].z);
                acc[i][1].w = fmaf(a[i], b1.w, acc[i][1].w);
            }
        }
        __syncthreads();                      // buf^1 fully written, buf reusable
        buf ^= 1;
    }

    float4 bv0 = make_float4(0.f, 0.f, 0.f, 0.f);
    float4 bv1 = bv0;
    if (HAS_BIAS) {
        bv0 = *(const float4*)&bias[m0 + m_sub];
        bv1 = *(const float4*)&bias[m0 + m_sub + 4];
    }

    #pragma unroll
    for (int i = 0; i < 8; i++) {
        int p = p0 + p_sub + i;
        if (p >= Plen) break;
        size_t pg = (size_t)z * Plen + p;
        float4 v0 = acc[i][0];
        float4 v1 = acc[i][1];
        if (HAS_BIAS) {
            v0.x += bv0.x; v0.y += bv0.y; v0.z += bv0.z; v0.w += bv0.w;
            v1.x += bv1.x; v1.y += bv1.y; v1.z += bv1.z; v1.w += bv1.w;
        }
        if (HAS_RELU) {
            v0.x = fmaxf(v0.x, 0.f); v0.y = fmaxf(v0.y, 0.f);
            v0.z = fmaxf(v0.z, 0.f); v0.w = fmaxf(v0.w, 0.f);
            v1.x = fmaxf(v1.x, 0.f); v1.y = fmaxf(v1.y, 0.f);
            v1.z = fmaxf(v1.z, 0.f); v1.w = fmaxf(v1.w, 0.f);
        }
        if (HAS_ADD) {
            float4 a0 = *(const float4*)&addin[pg * M + m0 + m_sub];
            float4 a1 = *(const float4*)&addin[pg * M + m0 + m_sub + 4];
            v0.x += a0.x; v0.y += a0.y; v0.z += a0.z; v0.w += a0.w;
            v1.x += a1.x; v1.y += a1.y; v1.z += a1.z; v1.w += a1.w;
        }
        *(float4*)&C[pg * M + m0 + m_sub]     = v0;
        *(float4*)&C[pg * M + m0 + m_sub + 4] = v1;
    }
}

// ---------------------------------------------------------------------------
// Local 7x7 window attention. Block = 8x8 pixel tile x 2-head group (64 ch),
// 128 threads. K,V halo (14x14 x 64ch) in smem (106KB -> 2 CTA/SM).
// warp = (head, 32 pixels); each thread owns one (pixel, head).
// ---------------------------------------------------------------------------
__global__ __launch_bounds__(128)
void attn_k(const float* __restrict__ Q, const float* __restrict__ K,
            const float* __restrict__ V, float* __restrict__ O)
{
    extern __shared__ float sm[];
    float* Ks = sm;
    float* Vs = sm + NPOS * STR;

    const int t   = threadIdx.x;
    const int bz  = blockIdx.z;
    const int b   = bz >> 2;
    const int hg  = bz & 3;            // head group (2 heads / 64 channels)
    const int tx0 = blockIdx.x * 8;
    const int ty0 = blockIdx.y * 8;
    const int chb = hg * 64;

    // stage halo: 196 positions x 64 channels (16 float4 each), replicate-clamped
    for (int idx = t; idx < NPOS * 16; idx += 128) {
        int pos = idx >> 4;
        int c4  = (idx & 15) * 4;
        int hy  = pos / 14;
        int hx  = pos - hy * 14;
        int gy  = ty0 + hy - 3; gy = max(0, min(HDIM - 1, gy));
        int gx  = tx0 + hx - 3; gx = max(0, min(WDIM - 1, gx));
        size_t gp = ((size_t)b * HWC + gy * WDIM + gx) * 256 + chb + c4;
        float4 kv = *(const float4*)(K + gp);
        float4 vv = *(const float4*)(V + gp);
        int so = pos * STR + c4;
        *(float4*)&Ks[so] = kv;
        *(float4*)&Vs[so] = vv;
    }
    __syncthreads();

    const int wid  = t >> 5;                  // 0..3
    const int lane = t & 31;
    const int hl   = wid & 1;                 // head within group (0..1)
    const int half = wid >> 1;                // 0..1
    const int row  = half * 4 + (lane >> 3);  // 0..7
    const int col  = lane & 7;                // 0..7

    size_t pg = (size_t)b * HWC + (ty0 + row) * WDIM + (tx0 + col);
    const float* qp = Q + pg * 256 + chb + hl * 32;

    float4 q4[8];
    #pragma unroll
    for (int d4 = 0; d4 < 8; d4++) {
        float4 v = *(const float4*)(qp + d4 * 4);
        const float sc = 0.17677669529663687f; // HD^-0.5
        v.x *= sc; v.y *= sc; v.z *= sc; v.w *= sc;
        q4[d4] = v;
    }

    float lg[49];
    #pragma unroll
    for (int wi = 0; wi < 7; wi++) {
        #pragma unroll
        for (int wj = 0; wj < 7; wj++) {
            const float4* kp =
                (const float4*)&Ks[((row + wi) * 14 + col + wj) * STR + hl * 32];
            float acc = 0.f;
            #pragma unroll
            for (int d4 = 0; d4 < 8; d4++) {
                float4 k = kp[d4];
                acc = fmaf(q4[d4].x, k.x, acc);
                acc = fmaf(q4[d4].y, k.y, acc);
                acc = fmaf(q4[d4].z, k.z, acc);
                acc = fmaf(q4[d4].w, k.w, acc);
            }
            lg[wi * 7 + wj] = acc;
        }
    }

    float mx = lg[0];
    #pragma unroll
    for (int k = 1; k < 49; k++) mx = fmaxf(mx, lg[k]);
    float s = 0.f;
    #pragma unroll
    for (int k = 0; k < 49; k++) { float e = __expf(lg[k] - mx); lg[k] = e; s += e; }
    float inv = 1.f / s;

    float4 o4[8];
    #pragma unroll
    for (int d4 = 0; d4 < 8; d4++) o4[d4] = make_float4(0.f, 0.f, 0.f, 0.f);
    #pragma unroll
    for (int wi = 0; wi < 7; wi++) {
        #pragma unroll
        for (int wj = 0; wj < 7; wj++) {
            float w = lg[wi * 7 + wj] * inv;
            const float4* vp =
                (const float4*)&Vs[((row + wi) * 14 + col + wj) * STR + hl * 32];
            #pragma unroll
            for (int d4 = 0; d4 < 8; d4++) {
                float4 v = vp[d4];
                o4[d4].x = fmaf(w, v.x, o4[d4].x);
                o4[d4].y = fmaf(w, v.y, o4[d4].y);
                o4[d4].z = fmaf(w, v.z, o4[d4].z);
                o4[d4].w = fmaf(w, v.w, o4[d4].w);
            }
        }
    }

    float* op = O + pg * 256 + chb + hl * 32;
    #pragma unroll
    for (int d4 = 0; d4 < 8; d4++)
        *(float4*)(op + d4 * 4) = o4[d4];
}

// ---------------------------------------------------------------------------
// LayerNorm over 256 channels, pixel-major in -> pixel-major out. Warp/pixel.
// ---------------------------------------------------------------------------
__global__ __launch_bounds__(256)
void ln_k(const float* __restrict__ in, const float* __restrict__ g,
          const float* __restrict__ bb, float* __restrict__ out, int n)
{
    int warp = threadIdx.x >> 5, lane = threadIdx.x & 31;
    int p = blockIdx.x * 8 + warp;
    if (p >= n) return;
    const float* ip = in + (size_t)p * 256;
    int c0 = lane * 4, c1 = 128 + lane * 4;
    float4 v0 = *(const float4*)(ip + c0);
    float4 v1 = *(const float4*)(ip + c1);
    float s  = v0.x + v0.y + v0.z + v0.w + v1.x + v1.y + v1.z + v1.w;
    float ss = v0.x*v0.x + v0.y*v0.y + v0.z*v0.z + v0.w*v0.w
             + v1.x*v1.x + v1.y*v1.y + v1.z*v1.z + v1.w*v1.w;
    #pragma unroll
    for (int o = 16; o; o >>= 1) {
        s  += __shfl_xor_sync(0xffffffffu, s,  o);
        ss += __shfl_xor_sync(0xffffffffu, ss, o);
    }
    float mu  = s * (1.f / 256.f);
    float var = ss * (1.f / 256.f) - mu * mu;
    float r   = rsqrtf(var + 1e-5f);

    float* op = out + (size_t)p * 256;
    float4 g0 = *(const float4*)(g + c0),  g1v = *(const float4*)(g + c1);
    float4 b0 = *(const float4*)(bb + c0), b1v = *(const float4*)(bb + c1);
    float4 o0, o1;
    o0.x = (v0.x - mu) * r * g0.x + b0.x;  o0.y = (v0.y - mu) * r * g0.y + b0.y;
    o0.z = (v0.z - mu) * r * g0.z + b0.z;  o0.w = (v0.w - mu) * r * g0.w + b0.w;
    o1.x = (v1.x - mu) * r * g1v.x + b1v.x; o1.y = (v1.y - mu) * r * g1v.y + b1v.y;
    o1.z = (v1.z - mu) * r * g1v.z + b1v.z; o1.w = (v1.w - mu) * r * g1v.w + b1v.w;
    *(float4*)(op + c0) = o0;
    *(float4*)(op + c1) = o1;
}

// ---------------------------------------------------------------------------
// Final LayerNorm + NHWC->NCHW transposed store (coalesced via smem staging).
// Block = 32 consecutive pixels of one batch; 8 warps x 4 pixels.
// ---------------------------------------------------------------------------
__global__ __launch_bounds__(256)
void ln2t_k(const float* __restrict__ in, const float* __restrict__ g,
            const float* __restrict__ bb, float* __restrict__ out)
{
    __shared__ float smt[32][257];
    int warp = threadIdx.x >> 5, lane = threadIdx.x & 31;
    int hw0 = blockIdx.x * 32;
    int b   = blockIdx.y;
    int c0 = lane * 4, c1 = 128 + lane * 4;

    float4 g0 = *(const float4*)(g + c0),  g1v = *(const float4*)(g + c1);
    float4 b0 = *(const float4*)(bb + c0), b1v = *(const float4*)(bb + c1);

    #pragma unroll
    for (int j = 0; j < 4; j++) {
        int pl = warp * 4 + j;
        const float* ip = in + ((size_t)b * HWC + hw0 + pl) * 256;
        float4 v0 = *(const float4*)(ip + c0);
        float4 v1 = *(const float4*)(ip + c1);
        float s  = v0.x + v0.y + v0.z + v0.w + v1.x + v1.y + v1.z + v1.w;
        float ss = v0.x*v0.x + v0.y*v0.y + v0.z*v0.z + v0.w*v0.w
                 + v1.x*v1.x + v1.y*v1.y + v1.z*v1.z + v1.w*v1.w;
        #pragma unroll
        for (int o = 16; o; o >>= 1) {
            s  += __shfl_xor_sync(0xffffffffu, s,  o);
            ss += __shfl_xor_sync(0xffffffffu, ss, o);
        }
        float mu  = s * (1.f / 256.f);
        float var = ss * (1.f / 256.f) - mu * mu;
        float r   = rsqrtf(var + 1e-5f);
        smt[pl][c0 + 0] = (v0.x - mu) * r * g0.x + b0.x;
        smt[pl][c0 + 1] = (v0.y - mu) * r * g0.y + b0.y;
        smt[pl][c0 + 2] = (v0.z - mu) * r * g0.z + b0.z;
        smt[pl][c0 + 3] = (v0.w - mu) * r * g0.w + b0.w;
        smt[pl][c1 + 0] = (v1.x - mu) * r * g1v.x + b1v.x;
        smt[pl][c1 + 1] = (v1.y - mu) * r * g1v.y + b1v.y;
        smt[pl][c1 + 2] = (v1.z - mu) * r * g1v.z + b1v.z;
        smt[pl][c1 + 3] = (v1.w - mu) * r * g1v.w + b1v.w;
    }
    __syncthreads();

    #pragma unroll 4
    for (int cc = 0; cc < 32; cc++) {
        int c = warp * 32 + cc;
        out[((size_t)b * 256 + c) * HWC + hw0 + lane] = smt[lane][c];
    }
}

// ---------------------------------------------------------------------------
extern "C" void kernel_launch(void* const* d_in, const int* in_sizes, int n_in,
                              void* d_out, int out_size)
{
    const float* F_lidar = (const float*)d_in[0];
    const float* F_cam   = (const float*)d_in[1];
    const float* Wq  = (const float*)d_in[2];
    const float* Wk  = (const float*)d_in[3];
    const float* Wv  = (const float*)d_in[4];
    const float* Wo  = (const float*)d_in[5];
    const float* Wr  = (const float*)d_in[6];
    const float* g1  = (const float*)d_in[7];
    const float* b1  = (const float*)d_in[8];
    const float* g2  = (const float*)d_in[9];
    const float* b2  = (const float*)d_in[10];
    const float* W1  = (const float*)d_in[11];
    const float* bf1 = (const float*)d_in[12];
    const float* W2  = (const float*)d_in[13];
    const float* bf2 = (const float*)d_in[14];
    float* out = (float*)d_out;

    float *Qb, *Kb, *Vb, *Rb, *At, *Z1, *X, *Y, *Z2;
    cudaGetSymbolAddress((void**)&Qb, g_Qb);
    cudaGetSymbolAddress((void**)&Kb, g_Kb);
    cudaGetSymbolAddress((void**)&Vb, g_Vb);
    cudaGetSymbolAddress((void**)&Rb, g_Rb);
    cudaGetSymbolAddress((void**)&At, g_At);
    cudaGetSymbolAddress((void**)&Z1, g_Z1);
    cudaGetSymbolAddress((void**)&X,  g_X);
    cudaGetSymbolAddress((void**)&Y,  g_Y);
    cudaGetSymbolAddress((void**)&Z2, g_Z2);

    cudaFuncSetAttribute(attn_k, cudaFuncAttributeMaxDynamicSharedMemorySize, ATTN_SMEM);

    dim3 blk(256);
    dim3 gProj(2, 313, 2);   // M/128, ceil(40000/128), B

    // projections: C[p][m] = sum_k W[m][k] * F[b][k][p]
    gemm_k<true, true, false, false, false><<<gProj, blk>>>(
        F_lidar, Wq, nullptr, nullptr, Qb, 256, 64, HWC, (size_t)64 * HWC);
    gemm_k<true, true, false, false, false><<<gProj, blk>>>(
        F_cam, Wk, nullptr, nullptr, Kb, 256, 256, HWC, (size_t)256 * HWC);
    gemm_k<true, true, false, false, false><<<gProj, blk>>>(
        F_cam, Wv, nullptr, nullptr, Vb, 256, 256, HWC, (size_t)256 * HWC);
    gemm_k<true, true, false, false, false><<<gProj, blk>>>(
        F_lidar, Wr, nullptr, nullptr, Rb, 256, 64, HWC, (size_t)64 * HWC);

    // local window attention (2-head groups, 2 CTA/SM)
    attn_k<<<dim3(25, 25, 8), 128, ATTN_SMEM>>>(Qb, Kb, Vb, At);

    // Wo projection + residual add
    gemm_k<false, true, false, false, true><<<dim3(2, 625, 1), blk>>>(
        At, Wo, nullptr, Rb, Z1, 256, 256, PTOT, 0);

    ln_k<<<10000, blk>>>(Z1, g1, b1, X, PTOT);

    // FFN
    gemm_k<false, false, true, true, false><<<dim3(8, 625, 1), blk>>>(
        X, W1, bf1, nullptr, Y, 1024, 256, PTOT, 0);
    gemm_k<false, false, true, false, true><<<dim3(2, 625, 1), blk>>>(
        Y, W2, bf2, X, Z2, 256, 1024, PTOT, 0);

    // final LN + NCHW transpose
    ln2t_k<<<dim3(1250, 2), blk>>>(Z2, g2, b2, out);
}

// round 15
// speedup vs baseline: 1.1177x; 1.1177x over previous
#include <cuda_runtime.h>
#include <math.h>

// ---------------------------------------------------------------------------
// LocalWindowAttentionFusion — fp32, 64x128 double-buffered GEMMs (8x4 uTile,
// measured-good R2 config) + 2-head-group attention (2 CTA/SM).
//   B=2, H=W=200, C1=64, C2=256, C3=256, HEADS=8, HD=32, WS=7, PAD=3
// ---------------------------------------------------------------------------

#define HWC   40000          // H*W
#define PTOT  80000          // B*H*W
#define HDIM  200
#define WDIM  200
#define NPOS  196            // 14*14 halo positions
#define STR   68             // smem row stride for 64ch group (mult of 4)
#define ATTN_SMEM (2 * NPOS * STR * 4)

// -------- scratch (device globals: allocation inside kernel_launch is banned)
__device__ float g_Qb[(size_t)PTOT * 256];
__device__ float g_Kb[(size_t)PTOT * 256];
__device__ float g_Vb[(size_t)PTOT * 256];
__device__ float g_Rb[(size_t)PTOT * 256];
__device__ float g_At[(size_t)PTOT * 256];
__device__ float g_Z1[(size_t)PTOT * 256];
__device__ float g_X [(size_t)PTOT * 256];
__device__ float g_Y [(size_t)PTOT * 1024];
__device__ float g_Z2[(size_t)PTOT * 256];

// ---------------------------------------------------------------------------
// fp32 GEMM producing pixel-major C[p][m], double-buffered smem.
//   X_CHW : X is channel-major X[k][p] (per batch, ldX = Plen), else X[p][k]
//   W_MK  : weight stored W[m][k] (torch conv style), else W[k][m]
// BM=64, BP=128, BK=16, 256 threads, 8x4 micro-tile / thread. (regs ~73, occ 35%)
// ---------------------------------------------------------------------------
template<bool X_CHW, bool W_MK, bool HAS_BIAS, bool HAS_RELU, bool HAS_ADD>
__global__ __launch_bounds__(256)
void gemm_k(const float* __restrict__ X, const float* __restrict__ W,
            const float* __restrict__ bias, const float* __restrict__ addin,
            float* __restrict__ C, int M, int Kd, int Plen, size_t xBatchStride)
{
    __shared__ float As[2][16][132];
    __shared__ float Bs[2][16][68];

    const int t     = threadIdx.x;
    const int tx    = t & 15;          // m direction
    const int ty    = t >> 4;          // p direction
    const int m_sub = tx * 4;
    const int p_sub = ty * 8;
    const int m0    = blockIdx.x * 64;
    const int p0    = blockIdx.y * 128;
    const int z     = blockIdx.z;
    const float* Xb = X + (size_t)z * xBatchStride;

    auto loadTile = [&](int k0, int buf) {
        if (X_CHW) {
            #pragma unroll
            for (int r = 0; r < 2; r++) {
                int idx = t + r * 256;           // 512 float4 per step
                int kk  = idx >> 5;
                int pp  = (idx & 31) * 4;
                int p   = p0 + pp;
                const float* src = Xb + (size_t)(k0 + kk) * Plen + p;
                float4 v;
                if (p + 3 < Plen) {
                    v = *(const float4*)src;
                } else {
                    v.x = (p + 0 < Plen) ? src[0] : 0.f;
                    v.y = (p + 1 < Plen) ? src[1] : 0.f;
                    v.z = (p + 2 < Plen) ? src[2] : 0.f;
                    v.w = (p + 3 < Plen) ? src[3] : 0.f;
                }
                *(float4*)&As[buf][kk][pp] = v;
            }
        } else {
            #pragma unroll
            for (int r = 0; r < 2; r++) {
                int idx = t + r * 256;
                int pp  = idx >> 2;
                int kk  = (idx & 3) * 4;
                float4 v = *(const float4*)(Xb + (size_t)(p0 + pp) * Kd + k0 + kk);
                As[buf][kk + 0][pp] = v.x;
                As[buf][kk + 1][pp] = v.y;
                As[buf][kk + 2][pp] = v.z;
                As[buf][kk + 3][pp] = v.w;
            }
        }
        if (W_MK) {
            int mm = t >> 2;
            int kk = (t & 3) * 4;
            float4 v = *(const float4*)(W + (size_t)(m0 + mm) * Kd + k0 + kk);
            Bs[buf][kk + 0][mm] = v.x;
            Bs[buf][kk + 1][mm] = v.y;
            Bs[buf][kk + 2][mm] = v.z;
            Bs[buf][kk + 3][mm] = v.w;
        } else {
            int kk = t >> 4;
            int mm = (t & 15) * 4;
            *(float4*)&Bs[buf][kk][mm] = *(const float4*)(W + (size_t)(k0 + kk) * M + m0 + mm);
        }
    };

    float4 acc[8];
    #pragma unroll
    for (int i = 0; i < 8; i++) acc[i] = make_float4(0.f, 0.f, 0.f, 0.f);

    int buf = 0;
    loadTile(0, 0);
    __syncthreads();

    for (int k0 = 16; k0 <= Kd; k0 += 16) {
        if (k0 < Kd) loadTile(k0, buf ^ 1);   // prefetch next tile (no barrier needed)

        #pragma unroll
        for (int kk = 0; kk < 16; kk++) {
            float4 b  = *(float4*)&Bs[buf][kk][m_sub];
            float4 a0 = *(float4*)&As[buf][kk][p_sub];
            float4 a1 = *(float4*)&As[buf][kk][p_sub + 4];
            float  a[8] = {a0.x, a0.y, a0.z, a0.w, a1.x, a1.y, a1.z, a1.w};
            #pragma unroll
            for (int i = 0; i < 8; i++) {
                acc[i].x = fmaf(a[i], b.x, acc[i].x);
                acc[i].y = fmaf(a[i], b.y, acc[i].y);
                acc[i].z = fmaf(a[i], b.z, acc[i].z);
                acc[i].w = fmaf(a[i], b.w, acc[i].w);
            }
        }
        __syncthreads();                      // loads to buf^1 done, buf reusable
        buf ^= 1;
    }

    float4 bv = make_float4(0.f, 0.f, 0.f, 0.f);
    if (HAS_BIAS) bv = *(const float4*)&bias[m0 + m_sub];

    #pragma unroll
    for (int i = 0; i < 8; i++) {
        int p = p0 + p_sub + i;
        if (p >= Plen) break;
        size_t pg = (size_t)z * Plen + p;
        float4 v = acc[i];
        if (HAS_BIAS) { v.x += bv.x; v.y += bv.y; v.z += bv.z; v.w += bv.w; }
        if (HAS_RELU) {
            v.x = fmaxf(v.x, 0.f); v.y = fmaxf(v.y, 0.f);
            v.z = fmaxf(v.z, 0.f); v.w = fmaxf(v.w, 0.f);
        }
        if (HAS_ADD) {
            float4 a = *(const float4*)&addin[pg * M + m0 + m_sub];
            v.x += a.x; v.y += a.y; v.z += a.z; v.w += a.w;
        }
        *(float4*)&C[pg * M + m0 + m_sub] = v;
    }
}

// ---------------------------------------------------------------------------
// Local 7x7 window attention. Block = 8x8 pixel tile x 2-head group (64 ch),
// 128 threads. K,V halo (14x14 x 64ch) in smem (106KB -> 2 CTA/SM).
// warp = (head, 32 pixels); each thread owns one (pixel, head).
// ---------------------------------------------------------------------------
__global__ __launch_bounds__(128)
void attn_k(const float* __restrict__ Q, const float* __restrict__ K,
            const float* __restrict__ V, float* __restrict__ O)
{
    extern __shared__ float sm[];
    float* Ks = sm;
    float* Vs = sm + NPOS * STR;

    const int t   = threadIdx.x;
    const int bz  = blockIdx.z;
    const int b   = bz >> 2;
    const int hg  = bz & 3;            // head group (2 heads / 64 channels)
    const int tx0 = blockIdx.x * 8;
    const int ty0 = blockIdx.y * 8;
    const int chb = hg * 64;

    // stage halo: 196 positions x 64 channels (16 float4 each), replicate-clamped
    for (int idx = t; idx < NPOS * 16; idx += 128) {
        int pos = idx >> 4;
        int c4  = (idx & 15) * 4;
        int hy  = pos / 14;
        int hx  = pos - hy * 14;
        int gy  = ty0 + hy - 3; gy = max(0, min(HDIM - 1, gy));
        int gx  = tx0 + hx - 3; gx = max(0, min(WDIM - 1, gx));
        size_t gp = ((size_t)b * HWC + gy * WDIM + gx) * 256 + chb + c4;
        float4 kv = *(const float4*)(K + gp);
        float4 vv = *(const float4*)(V + gp);
        int so = pos * STR + c4;
        *(float4*)&Ks[so] = kv;
        *(float4*)&Vs[so] = vv;
    }
    __syncthreads();

    const int wid  = t >> 5;                  // 0..3
    const int lane = t & 31;
    const int hl   = wid & 1;                 // head within group (0..1)
    const int half = wid >> 1;                // 0..1
    const int row  = half * 4 + (lane >> 3);  // 0..7
    const int col  = lane & 7;                // 0..7

    size_t pg = (size_t)b * HWC + (ty0 + row) * WDIM + (tx0 + col);
    const float* qp = Q + pg * 256 + chb + hl * 32;

    float4 q4[8];
    #pragma unroll
    for (int d4 = 0; d4 < 8; d4++) {
        float4 v = *(const float4*)(qp + d4 * 4);
        const float sc = 0.17677669529663687f; // HD^-0.5
        v.x *= sc; v.y *= sc; v.z *= sc; v.w *= sc;
        q4[d4] = v;
    }

    float lg[49];
    #pragma unroll
    for (int wi = 0; wi < 7; wi++) {
        #pragma unroll
        for (int wj = 0; wj < 7; wj++) {
            const float4* kp =
                (const float4*)&Ks[((row + wi) * 14 + col + wj) * STR + hl * 32];
            float acc = 0.f;
            #pragma unroll
            for (int d4 = 0; d4 < 8; d4++) {
                float4 k = kp[d4];
                acc = fmaf(q4[d4].x, k.x, acc);
                acc = fmaf(q4[d4].y, k.y, acc);
                acc = fmaf(q4[d4].z, k.z, acc);
                acc = fmaf(q4[d4].w, k.w, acc);
            }
            lg[wi * 7 + wj] = acc;
        }
    }

    float mx = lg[0];
    #pragma unroll
    for (int k = 1; k < 49; k++) mx = fmaxf(mx, lg[k]);
    float s = 0.f;
    #pragma unroll
    for (int k = 0; k < 49; k++) { float e = __expf(lg[k] - mx); lg[k] = e; s += e; }
    float inv = 1.f / s;

    float4 o4[8];
    #pragma unroll
    for (int d4 = 0; d4 < 8; d4++) o4[d4] = make_float4(0.f, 0.f, 0.f, 0.f);
    #pragma unroll
    for (int wi = 0; wi < 7; wi++) {
        #pragma unroll
        for (int wj = 0; wj < 7; wj++) {
            float w = lg[wi * 7 + wj] * inv;
            const float4* vp =
                (const float4*)&Vs[((row + wi) * 14 + col + wj) * STR + hl * 32];
            #pragma unroll
            for (int d4 = 0; d4 < 8; d4++) {
                float4 v = vp[d4];
                o4[d4].x = fmaf(w, v.x, o4[d4].x);
                o4[d4].y = fmaf(w, v.y, o4[d4].y);
                o4[d4].z = fmaf(w, v.z, o4[d4].z);
                o4[d4].w = fmaf(w, v.w, o4[d4].w);
            }
        }
    }

    float* op = O + pg * 256 + chb + hl * 32;
    #pragma unroll
    for (int d4 = 0; d4 < 8; d4++)
        *(float4*)(op + d4 * 4) = o4[d4];
}

// ---------------------------------------------------------------------------
// LayerNorm over 256 channels, pixel-major in -> pixel-major out. Warp/pixel.
// ---------------------------------------------------------------------------
__global__ __launch_bounds__(256)
void ln_k(const float* __restrict__ in, const float* __restrict__ g,
          const float* __restrict__ bb, float* __restrict__ out, int n)
{
    int warp = threadIdx.x >> 5, lane = threadIdx.x & 31;
    int p = blockIdx.x * 8 + warp;
    if (p >= n) return;
    const float* ip = in + (size_t)p * 256;
    int c0 = lane * 4, c1 = 128 + lane * 4;
    float4 v0 = *(const float4*)(ip + c0);
    float4 v1 = *(const float4*)(ip + c1);
    float s  = v0.x + v0.y + v0.z + v0.w + v1.x + v1.y + v1.z + v1.w;
    float ss = v0.x*v0.x + v0.y*v0.y + v0.z*v0.z + v0.w*v0.w
             + v1.x*v1.x + v1.y*v1.y + v1.z*v1.z + v1.w*v1.w;
    #pragma unroll
    for (int o = 16; o; o >>= 1) {
        s  += __shfl_xor_sync(0xffffffffu, s,  o);
        ss += __shfl_xor_sync(0xffffffffu, ss, o);
    }
    float mu  = s * (1.f / 256.f);
    float var = ss * (1.f / 256.f) - mu * mu;
    float r   = rsqrtf(var + 1e-5f);

    float* op = out + (size_t)p * 256;
    float4 g0 = *(const float4*)(g + c0),  g1v = *(const float4*)(g + c1);
    float4 b0 = *(const float4*)(bb + c0), b1v = *(const float4*)(bb + c1);
    float4 o0, o1;
    o0.x = (v0.x - mu) * r * g0.x + b0.x;  o0.y = (v0.y - mu) * r * g0.y + b0.y;
    o0.z = (v0.z - mu) * r * g0.z + b0.z;  o0.w = (v0.w - mu) * r * g0.w + b0.w;
    o1.x = (v1.x - mu) * r * g1v.x + b1v.x; o1.y = (v1.y - mu) * r * g1v.y + b1v.y;
    o1.z = (v1.z - mu) * r * g1v.z + b1v.z; o1.w = (v1.w - mu) * r * g1v.w + b1v.w;
    *(float4*)(op + c0) = o0;
    *(float4*)(op + c1) = o1;
}

// ---------------------------------------------------------------------------
// Final LayerNorm + NHWC->NCHW transposed store (coalesced via smem staging).
// Block = 32 consecutive pixels of one batch; 8 warps x 4 pixels.
// ---------------------------------------------------------------------------
__global__ __launch_bounds__(256)
void ln2t_k(const float* __restrict__ in, const float* __restrict__ g,
            const float* __restrict__ bb, float* __restrict__ out)
{
    __shared__ float smt[32][257];
    int warp = threadIdx.x >> 5, lane = threadIdx.x & 31;
    int hw0 = blockIdx.x * 32;
    int b   = blockIdx.y;
    int c0 = lane * 4, c1 = 128 + lane * 4;

    float4 g0 = *(const float4*)(g + c0),  g1v = *(const float4*)(g + c1);
    float4 b0 = *(const float4*)(bb + c0), b1v = *(const float4*)(bb + c1);

    #pragma unroll
    for (int j = 0; j < 4; j++) {
        int pl = warp * 4 + j;
        const float* ip = in + ((size_t)b * HWC + hw0 + pl) * 256;
        float4 v0 = *(const float4*)(ip + c0);
        float4 v1 = *(const float4*)(ip + c1);
        float s  = v0.x + v0.y + v0.z + v0.w + v1.x + v1.y + v1.z + v1.w;
        float ss = v0.x*v0.x + v0.y*v0.y + v0.z*v0.z + v0.w*v0.w
                 + v1.x*v1.x + v1.y*v1.y + v1.z*v1.z + v1.w*v1.w;
        #pragma unroll
        for (int o = 16; o; o >>= 1) {
            s  += __shfl_xor_sync(0xffffffffu, s,  o);
            ss += __shfl_xor_sync(0xffffffffu, ss, o);
        }
        float mu  = s * (1.f / 256.f);
        float var = ss * (1.f / 256.f) - mu * mu;
        float r   = rsqrtf(var + 1e-5f);
        smt[pl][c0 + 0] = (v0.x - mu) * r * g0.x + b0.x;
        smt[pl][c0 + 1] = (v0.y - mu) * r * g0.y + b0.y;
        smt[pl][c0 + 2] = (v0.z - mu) * r * g0.z + b0.z;
        smt[pl][c0 + 3] = (v0.w - mu) * r * g0.w + b0.w;
        smt[pl][c1 + 0] = (v1.x - mu) * r * g1v.x + b1v.x;
        smt[pl][c1 + 1] = (v1.y - mu) * r * g1v.y + b1v.y;
        smt[pl][c1 + 2] = (v1.z - mu) * r * g1v.z + b1v.z;
        smt[pl][c1 + 3] = (v1.w - mu) * r * g1v.w + b1v.w;
    }
    __syncthreads();

    #pragma unroll 4
    for (int cc = 0; cc < 32; cc++) {
        int c = warp * 32 + cc;
        out[((size_t)b * 256 + c) * HWC + hw0 + lane] = smt[lane][c];
    }
}

// ---------------------------------------------------------------------------
extern "C" void kernel_launch(void* const* d_in, const int* in_sizes, int n_in,
                              void* d_out, int out_size)
{
    const float* F_lidar = (const float*)d_in[0];
    const float* F_cam   = (const float*)d_in[1];
    const float* Wq  = (const float*)d_in[2];
    const float* Wk  = (const float*)d_in[3];
    const float* Wv  = (const float*)d_in[4];
    const float* Wo  = (const float*)d_in[5];
    const float* Wr  = (const float*)d_in[6];
    const float* g1  = (const float*)d_in[7];
    const float* b1  = (const float*)d_in[8];
    const float* g2  = (const float*)d_in[9];
    const float* b2  = (const float*)d_in[10];
    const float* W1  = (const float*)d_in[11];
    const float* bf1 = (const float*)d_in[12];
    const float* W2  = (const float*)d_in[13];
    const float* bf2 = (const float*)d_in[14];
    float* out = (float*)d_out;

    float *Qb, *Kb, *Vb, *Rb, *At, *Z1, *X, *Y, *Z2;
    cudaGetSymbolAddress((void**)&Qb, g_Qb);
    cudaGetSymbolAddress((void**)&Kb, g_Kb);
    cudaGetSymbolAddress((void**)&Vb, g_Vb);
    cudaGetSymbolAddress((void**)&Rb, g_Rb);
    cudaGetSymbolAddress((void**)&At, g_At);
    cudaGetSymbolAddress((void**)&Z1, g_Z1);
    cudaGetSymbolAddress((void**)&X,  g_X);
    cudaGetSymbolAddress((void**)&Y,  g_Y);
    cudaGetSymbolAddress((void**)&Z2, g_Z2);

    cudaFuncSetAttribute(attn_k, cudaFuncAttributeMaxDynamicSharedMemorySize, ATTN_SMEM);

    dim3 blk(256);
    dim3 gProj(4, 313, 2);   // M/64, ceil(40000/128), B

    // projections: C[p][m] = sum_k W[m][k] * F[b][k][p]
    gemm_k<true, true, false, false, false><<<gProj, blk>>>(
        F_lidar, Wq, nullptr, nullptr, Qb, 256, 64, HWC, (size_t)64 * HWC);
    gemm_k<true, true, false, false, false><<<gProj, blk>>>(
        F_cam, Wk, nullptr, nullptr, Kb, 256, 256, HWC, (size_t)256 * HWC);
    gemm_k<true, true, false, false, false><<<gProj, blk>>>(
        F_cam, Wv, nullptr, nullptr, Vb, 256, 256, HWC, (size_t)256 * HWC);
    gemm_k<true, true, false, false, false><<<gProj, blk>>>(
        F_lidar, Wr, nullptr, nullptr, Rb, 256, 64, HWC, (size_t)64 * HWC);

    // local window attention (2-head groups, 2 CTA/SM)
    attn_k<<<dim3(25, 25, 8), 128, ATTN_SMEM>>>(Qb, Kb, Vb, At);

    // Wo projection + residual add
    gemm_k<false, true, false, false, true><<<dim3(4, 625, 1), blk>>>(
        At, Wo, nullptr, Rb, Z1, 256, 256, PTOT, 0);

    ln_k<<<10000, blk>>>(Z1, g1, b1, X, PTOT);

    // FFN
    gemm_k<false, false, true, true, false><<<dim3(16, 625, 1), blk>>>(
        X, W1, bf1, nullptr, Y, 1024, 256, PTOT, 0);
    gemm_k<false, false, true, false, true><<<dim3(4, 625, 1), blk>>>(
        Y, W2, bf2, X, Z2, 256, 1024, PTOT, 0);

    // final LN + NCHW transpose
    ln2t_k<<<dim3(1250, 2), blk>>>(Z2, g2, b2, out);
}